// round 1
// baseline (speedup 1.0000x reference)
#include <cuda_runtime.h>

#define NB     32
#define DIM    4096
#define FDIM   384
#define NGLOB  196
#define NLOC   36
#define SROWS  21760
#define TROWS  12544
#define TOTIND 30976

// ---------------- scratch (device globals; no allocations) ----------------
static __device__ float g_sfea[(size_t)SROWS * FDIM];   // normalized student feats
static __device__ float g_tfea[(size_t)TROWS * FDIM];   // normalized teacher feats
static __device__ float g_tcls[64 * DIM];               // teacher cls softmax
static __device__ float g_tm[TROWS];                    // teacher region row max
static __device__ float g_tz[TROWS];                    // teacher region row sumexp
static __device__ unsigned long long g_best[TOTIND];    // packed argmax (val<<32 | 0xFFFF-n)
static __device__ double g_acc;

// pair p: p in [0,9) -> i=0, j = (p==0?1:p+1) ; p in [9,18) -> i=1, j = (p==9?0:p-8)
__constant__ int c_POFF[18] = {0,6272,7424,8576,9728,10880,12032,13184,14336,
                               15488,21760,22912,24064,25216,26368,27520,28672,29824};
__constant__ int c_SOFF[10] = {0,6272,12544,13696,14848,16000,17152,18304,19456,20608};

// ---------------- helpers ----------------
__device__ __forceinline__ float read_temp(const int* ep) {
    int e = *ep;
    if (e < 0 || e > 100000) e = (int)__int_as_float(e);  // float-typed scalar fallback
    return (e < 30) ? (0.04f + 0.03f * (float)e * (1.0f / 29.0f)) : 0.07f;
}

__device__ __forceinline__ float warpRedSum(float v) {
#pragma unroll
    for (int o = 16; o > 0; o >>= 1) v += __shfl_xor_sync(0xffffffffu, v, o);
    return v;
}
__device__ __forceinline__ float warpRedMax(float v) {
#pragma unroll
    for (int o = 16; o > 0; o >>= 1) v = fmaxf(v, __shfl_xor_sync(0xffffffffu, v, o));
    return v;
}
// block of 256 threads (8 warps)
__device__ __forceinline__ float blkSum(float v, float* sh) {
    v = warpRedSum(v);
    if ((threadIdx.x & 31) == 0) sh[threadIdx.x >> 5] = v;
    __syncthreads();
    float r = sh[0]+sh[1]+sh[2]+sh[3]+sh[4]+sh[5]+sh[6]+sh[7];
    __syncthreads();
    return r;
}
__device__ __forceinline__ float blkMax(float v, float* sh) {
    v = warpRedMax(v);
    if ((threadIdx.x & 31) == 0) sh[threadIdx.x >> 5] = v;
    __syncthreads();
    float r = fmaxf(fmaxf(fmaxf(sh[0],sh[1]),fmaxf(sh[2],sh[3])),
                    fmaxf(fmaxf(sh[4],sh[5]),fmaxf(sh[6],sh[7])));
    __syncthreads();
    return r;
}
__device__ __forceinline__ unsigned int ordf(float f) {
    unsigned int u = __float_as_uint(f);
    return (u & 0x80000000u) ? ~u : (u | 0x80000000u);
}

// ---------------- K0: init ----------------
__global__ void k_init() {
    int i = blockIdx.x * blockDim.x + threadIdx.x;
    if (i == 0) g_acc = 0.0;
    if (i < TOTIND) g_best[i] = 0ull;
}

// ---------------- K1: L2-normalize feats ----------------
__global__ void __launch_bounds__(128) k_norm(const float* __restrict__ sf,
                                              const float* __restrict__ tf) {
    __shared__ float sh[4];
    int row = blockIdx.x;
    const float* src; float* dst;
    if (row < SROWS) { src = sf + (size_t)row * FDIM; dst = g_sfea + (size_t)row * FDIM; }
    else { int r = row - SROWS; src = tf + (size_t)r * FDIM; dst = g_tfea + (size_t)r * FDIM; }
    int t = threadIdx.x;
    float x0 = src[t], x1 = src[t + 128], x2 = src[t + 256];
    float ss = x0*x0 + x1*x1 + x2*x2;
    ss = warpRedSum(ss);
    if ((t & 31) == 0) sh[t >> 5] = ss;
    __syncthreads();
    float tot = sh[0] + sh[1] + sh[2] + sh[3];
    float inv = 1.0f / fmaxf(sqrtf(tot), 1e-12f);
    dst[t] = x0 * inv; dst[t + 128] = x1 * inv; dst[t + 256] = x2 * inv;
}

// ---------------- K2: teacher cls softmax (64 rows) ----------------
__global__ void __launch_bounds__(256) k_tcls(const float* __restrict__ tcls,
                                              const float* __restrict__ center,
                                              const int* __restrict__ ep) {
    __shared__ float sh[8];
    int row = blockIdx.x, tid = threadIdx.x;
    float it = 1.0f / read_temp(ep);
    const float4* xp = (const float4*)(tcls + (size_t)row * DIM);
    const float4* cp = (const float4*)center;
    float y[16];
#pragma unroll
    for (int k = 0; k < 4; k++) {
        float4 x = xp[tid + 256 * k], c = cp[tid + 256 * k];
        y[4*k+0] = (x.x - c.x) * it; y[4*k+1] = (x.y - c.y) * it;
        y[4*k+2] = (x.z - c.z) * it; y[4*k+3] = (x.w - c.w) * it;
    }
    float mx = -3.4e38f;
#pragma unroll
    for (int k = 0; k < 16; k++) mx = fmaxf(mx, y[k]);
    mx = blkMax(mx, sh);
    float se = 0.f;
#pragma unroll
    for (int k = 0; k < 16; k++) { y[k] = __expf(y[k] - mx); se += y[k]; }
    se = blkSum(se, sh);
    float inv = 1.0f / se;
    float4* op = (float4*)(g_tcls + (size_t)row * DIM);
#pragma unroll
    for (int k = 0; k < 4; k++)
        op[tid + 256 * k] = make_float4(y[4*k+0]*inv, y[4*k+1]*inv, y[4*k+2]*inv, y[4*k+3]*inv);
}

// ---------------- K3: teacher region softmax stats ----------------
__global__ void __launch_bounds__(256) k_stats(const float* __restrict__ treg,
                                               const float* __restrict__ cgrid,
                                               const int* __restrict__ ep) {
    __shared__ float sh[8];
    int row = blockIdx.x, tid = threadIdx.x;
    float it = 1.0f / read_temp(ep);
    const float4* xp = (const float4*)(treg + (size_t)row * DIM);
    const float4* cp = (const float4*)cgrid;
    float y[16];
#pragma unroll
    for (int k = 0; k < 4; k++) {
        float4 x = xp[tid + 256 * k], c = cp[tid + 256 * k];
        y[4*k+0] = (x.x - c.x) * it; y[4*k+1] = (x.y - c.y) * it;
        y[4*k+2] = (x.z - c.z) * it; y[4*k+3] = (x.w - c.w) * it;
    }
    float mx = -3.4e38f;
#pragma unroll
    for (int k = 0; k < 16; k++) mx = fmaxf(mx, y[k]);
    mx = blkMax(mx, sh);
    float se = 0.f;
#pragma unroll
    for (int k = 0; k < 16; k++) se += __expf(y[k] - mx);
    se = blkSum(se, sh);
    if (tid == 0) { g_tm[row] = mx; g_tz[row] = se; }
}

// ---------------- K4: cosine-sim argmax (register-tiled 16x32 per warp) ----------------
// warp-tiles: global pairs: 2 pairs * 32 b * (13 s-tiles * 7 n-tiles) = 5824
//             local  pairs: 16 pairs * 32 b * (3 * 7)              = 10752  -> 16576 warps
__global__ void __launch_bounds__(256) k_sim() {
    int gw = (blockIdx.x * 256 + threadIdx.x) >> 5;
    int lane = threadIdx.x & 31;
    int p, b, st, nt, S;
    if (gw < 5824) {
        int pb = gw / 91, t = gw % 91;
        p = (pb < 32) ? 0 : 9; b = pb & 31;
        st = t / 7; nt = t % 7; S = NGLOB;
    } else {
        int g = gw - 5824;
        int pb = g / 21, t = g % 21;
        int lp = pb >> 5; b = pb & 31;
        p = (lp < 8) ? (1 + lp) : (10 + (lp - 8));
        st = t / 7; nt = t % 7; S = NLOC;
    }
    int i = (p < 9) ? 0 : 1;
    int j = (p < 9) ? ((p == 0) ? 1 : p + 1) : ((p == 9) ? 0 : p - 8);

    int rgrp = lane >> 3, cgrp = lane & 7;
    int sbase = c_SOFF[j] + b * S + st * 16 + rgrp * 4;
    int tb = i * (NB * NGLOB) + b * NGLOB;

    const float4* ap[4]; const float4* bp[4];
#pragma unroll
    for (int r = 0; r < 4; r++) {
        int sr = sbase + r; if (sr > SROWS - 1) sr = SROWS - 1;
        ap[r] = (const float4*)(g_sfea + (size_t)sr * FDIM);
    }
#pragma unroll
    for (int c = 0; c < 4; c++) {
        int n = nt * 32 + cgrp * 4 + c; if (n > NGLOB - 1) n = NGLOB - 1;
        bp[c] = (const float4*)(g_tfea + (size_t)(tb + n) * FDIM);
    }
    float acc[4][4];
#pragma unroll
    for (int r = 0; r < 4; r++)
#pragma unroll
        for (int c = 0; c < 4; c++) acc[r][c] = 0.f;

    for (int k = 0; k < FDIM / 4; k++) {
        float4 av[4], bv[4];
#pragma unroll
        for (int r = 0; r < 4; r++) av[r] = ap[r][k];
#pragma unroll
        for (int c = 0; c < 4; c++) bv[c] = bp[c][k];
#pragma unroll
        for (int r = 0; r < 4; r++)
#pragma unroll
            for (int c = 0; c < 4; c++)
                acc[r][c] += av[r].x*bv[c].x + av[r].y*bv[c].y + av[r].z*bv[c].z + av[r].w*bv[c].w;
    }

#pragma unroll
    for (int r = 0; r < 4; r++) {
        int s = st * 16 + rgrp * 4 + r;
        unsigned long long key = 0ull;
#pragma unroll
        for (int c = 0; c < 4; c++) {
            int n = nt * 32 + cgrp * 4 + c;
            if (n < NGLOB) {
                unsigned long long k2 =
                    ((unsigned long long)ordf(acc[r][c]) << 32) | (unsigned)(0xFFFF - n);
                if (k2 > key) key = k2;
            }
        }
#pragma unroll
        for (int m = 1; m < 8; m <<= 1) {
            unsigned long long o = __shfl_xor_sync(0xffffffffu, key, m);
            if (o > key) key = o;
        }
        if (cgrp == 0 && s < S)
            atomicMax(&g_best[c_POFF[p] + b * S + s], key);
    }
}

// ---------------- K5: cls loss (18 pairs x 32 b) ----------------
__global__ void __launch_bounds__(256) k_cls(const float* __restrict__ scls) {
    __shared__ float sh[8];
    int p = blockIdx.x, b = blockIdx.y, tid = threadIdx.x;
    int i = (p < 9) ? 0 : 1;
    int j = (p < 9) ? ((p == 0) ? 1 : p + 1) : ((p == 9) ? 0 : p - 8);
    const float4* vp = (const float4*)(scls + (size_t)(j * NB + b) * DIM);
    const float4* qp = (const float4*)(g_tcls + (size_t)(i * NB + b) * DIM);
    float v[16], q[16];
#pragma unroll
    for (int k = 0; k < 4; k++) {
        float4 a = vp[tid + 256 * k], c = qp[tid + 256 * k];
        v[4*k+0] = a.x * 10.f; v[4*k+1] = a.y * 10.f; v[4*k+2] = a.z * 10.f; v[4*k+3] = a.w * 10.f;
        q[4*k+0] = c.x; q[4*k+1] = c.y; q[4*k+2] = c.z; q[4*k+3] = c.w;
    }
    float mx = -3.4e38f;
#pragma unroll
    for (int k = 0; k < 16; k++) mx = fmaxf(mx, v[k]);
    mx = blkMax(mx, sh);
    float se = 0.f, qv = 0.f;
#pragma unroll
    for (int k = 0; k < 16; k++) { se += __expf(v[k] - mx); qv += q[k] * v[k]; }
    se = blkSum(se, sh);
    qv = blkSum(qv, sh);
    if (tid == 0) {
        float lse = mx + logf(se);
        atomicAdd(&g_acc, (double)(lse - qv) * (0.5 / (32.0 * 18.0)));
    }
}

// ---------------- K6: region loss (fused lse + 1-2 gathered dots per row) -----
__global__ void __launch_bounds__(256) k_region(const float* __restrict__ sreg,
                                                const float* __restrict__ treg,
                                                const float* __restrict__ cgrid,
                                                const int* __restrict__ ep) {
    __shared__ float sh[8];
    int row = blockIdx.x, tid = threadIdx.x;
    int j, b, s;
    if (row < 12544) { j = row / 6272; int r = row - j * 6272; b = r / NGLOB; s = r - b * NGLOB; }
    else { int lr = row - 12544; j = 2 + lr / 1152; int r = lr % 1152; b = r / NLOC; s = r - b * NLOC; }
    int S = (j < 2) ? NGLOB : NLOC;
    float it = 1.0f / read_temp(ep);

    const float4* sp = (const float4*)(sreg + (size_t)row * DIM);
    float4 v[4];
#pragma unroll
    for (int k = 0; k < 4; k++) {
        float4 t = sp[tid + 256 * k];
        v[k] = make_float4(t.x * 10.f, t.y * 10.f, t.z * 10.f, t.w * 10.f);
    }
    float mx = -3.4e38f;
#pragma unroll
    for (int k = 0; k < 4; k++)
        mx = fmaxf(mx, fmaxf(fmaxf(v[k].x, v[k].y), fmaxf(v[k].z, v[k].w)));
    mx = blkMax(mx, sh);
    float se = 0.f;
#pragma unroll
    for (int k = 0; k < 4; k++)
        se += __expf(v[k].x - mx) + __expf(v[k].y - mx) + __expf(v[k].z - mx) + __expf(v[k].w - mx);
    se = blkSum(se, sh);
    float lse = mx + logf(se);

    float4 cg[4];
    const float4* cp = (const float4*)cgrid;
#pragma unroll
    for (int k = 0; k < 4; k++) cg[k] = cp[tid + 256 * k];

    int np, is0, is1;
    if (j == 0) { is0 = 1; is1 = 1; np = 1; }
    else if (j == 1) { is0 = 0; is1 = 0; np = 1; }
    else { is0 = 0; is1 = 1; np = 2; }

    float dotsum = 0.f;
    for (int qq = 0; qq < np; qq++) {
        int i = (qq == 0) ? is0 : is1;
        int p = (i == 0) ? ((j == 1) ? 0 : (j - 1)) : ((j == 0) ? 9 : (j + 8));
        unsigned long long key = g_best[c_POFF[p] + b * S + s];
        int n = 0xFFFF - (int)(key & 0xFFFFull);
        int trow = i * 6272 + b * NGLOB + n;
        float mT = g_tm[trow], invZ = 1.0f / g_tz[trow];
        const float4* tp = (const float4*)(treg + (size_t)trow * DIM);
        float part = 0.f;
#pragma unroll
        for (int k = 0; k < 4; k++) {
            float4 t = tp[tid + 256 * k]; float4 c = cg[k];
            part += __expf((t.x - c.x) * it - mT) * v[k].x;
            part += __expf((t.y - c.y) * it - mT) * v[k].y;
            part += __expf((t.z - c.z) * it - mT) * v[k].z;
            part += __expf((t.w - c.w) * it - mT) * v[k].w;
        }
        part = blkSum(part, sh);
        dotsum += part * invZ;
    }
    if (tid == 0) {
        double contrib = ((double)np * (double)lse - (double)dotsum)
                       * (0.5 / ((double)S * 32.0 * 18.0));
        atomicAdd(&g_acc, contrib);
    }
}

// ---------------- K7: finalize ----------------
__global__ void k_fin(float* out) { out[0] = (float)g_acc; }

// ---------------- launch ----------------
extern "C" void kernel_launch(void* const* d_in, const int* in_sizes, int n_in,
                              void* d_out, int out_size) {
    (void)in_sizes; (void)n_in; (void)out_size;
    const float* s_cls  = (const float*)d_in[0];
    const float* s_reg  = (const float*)d_in[1];
    const float* s_fea  = (const float*)d_in[2];
    const float* t_cls  = (const float*)d_in[3];
    const float* t_reg  = (const float*)d_in[4];
    const float* t_fea  = (const float*)d_in[5];
    const float* center = (const float*)d_in[6];
    const float* cgrid  = (const float*)d_in[7];
    const int*   ep     = (const int*)d_in[8];

    k_init<<<121, 256>>>();
    k_norm<<<SROWS + TROWS, 128>>>(s_fea, t_fea);
    k_tcls<<<64, 256>>>(t_cls, center, ep);
    k_stats<<<TROWS, 256>>>(t_reg, cgrid, ep);
    k_sim<<<2072, 256>>>();
    k_cls<<<dim3(18, NB), 256>>>(s_cls);
    k_region<<<SROWS, 256>>>(s_reg, t_reg, cgrid, ep);
    k_fin<<<1, 1>>>((float*)d_out);
}

// round 2
// speedup vs baseline: 2.8575x; 2.8575x over previous
#include <cuda_runtime.h>
#include <cuda_bf16.h>

#define NB     32
#define DIM    4096
#define FDIM   384
#define NGLOB  196
#define NLOC   36
#define SROWS  21760
#define TROWS  12544
#define TOTIND 30976

// ---------------- scratch (device globals; no allocations) ----------------
static __device__ float g_sfea[(size_t)SROWS * FDIM];   // normalized student feats
static __device__ float g_tfea[(size_t)TROWS * FDIM];   // normalized teacher feats
static __device__ float g_tcls[64 * DIM];               // teacher cls softmax
static __device__ uint2 g_tprob[(size_t)TROWS * DIM / 4]; // teacher region softmax, bf16 x4 packed
static __device__ unsigned long long g_best[TOTIND];    // packed argmax (val<<32 | 0xFFFF-n)
static __device__ double g_acc;

// pair p: p in [0,9) -> i=0, j = (p==0?1:p+1) ; p in [9,18) -> i=1, j = (p==9?0:p-8)
__constant__ int c_POFF[18] = {0,6272,7424,8576,9728,10880,12032,13184,14336,
                               15488,21760,22912,24064,25216,26368,27520,28672,29824};
__constant__ int c_SOFF[10] = {0,6272,12544,13696,14848,16000,17152,18304,19456,20608};

// ---------------- helpers ----------------
__device__ __forceinline__ float read_temp(const int* ep) {
    int e = *ep;
    if (e < 0 || e > 100000) e = (int)__int_as_float(e);  // float-typed scalar fallback
    return (e < 30) ? (0.04f + 0.03f * (float)e * (1.0f / 29.0f)) : 0.07f;
}
__device__ __forceinline__ float warpRedSum(float v) {
#pragma unroll
    for (int o = 16; o > 0; o >>= 1) v += __shfl_xor_sync(0xffffffffu, v, o);
    return v;
}
__device__ __forceinline__ float warpRedMax(float v) {
#pragma unroll
    for (int o = 16; o > 0; o >>= 1) v = fmaxf(v, __shfl_xor_sync(0xffffffffu, v, o));
    return v;
}
__device__ __forceinline__ float blkSum(float v, float* sh) {
    v = warpRedSum(v);
    if ((threadIdx.x & 31) == 0) sh[threadIdx.x >> 5] = v;
    __syncthreads();
    float r = sh[0]+sh[1]+sh[2]+sh[3]+sh[4]+sh[5]+sh[6]+sh[7];
    __syncthreads();
    return r;
}
__device__ __forceinline__ float blkMax(float v, float* sh) {
    v = warpRedMax(v);
    if ((threadIdx.x & 31) == 0) sh[threadIdx.x >> 5] = v;
    __syncthreads();
    float r = fmaxf(fmaxf(fmaxf(sh[0],sh[1]),fmaxf(sh[2],sh[3])),
                    fmaxf(fmaxf(sh[4],sh[5]),fmaxf(sh[6],sh[7])));
    __syncthreads();
    return r;
}
__device__ __forceinline__ unsigned int ordf(float f) {
    unsigned int u = __float_as_uint(f);
    return (u & 0x80000000u) ? ~u : (u | 0x80000000u);
}

// ---------------- K0: init ----------------
__global__ void k_init() {
    int i = blockIdx.x * blockDim.x + threadIdx.x;
    if (i == 0) g_acc = 0.0;
    if (i < TOTIND) g_best[i] = 0ull;
}

// ---------------- K1: L2-normalize feats ----------------
__global__ void __launch_bounds__(128) k_norm(const float* __restrict__ sf,
                                              const float* __restrict__ tf) {
    __shared__ float sh[4];
    int row = blockIdx.x;
    const float* src; float* dst;
    if (row < SROWS) { src = sf + (size_t)row * FDIM; dst = g_sfea + (size_t)row * FDIM; }
    else { int r = row - SROWS; src = tf + (size_t)r * FDIM; dst = g_tfea + (size_t)r * FDIM; }
    int t = threadIdx.x;
    float x0 = src[t], x1 = src[t + 128], x2 = src[t + 256];
    float ss = x0*x0 + x1*x1 + x2*x2;
    ss = warpRedSum(ss);
    if ((t & 31) == 0) sh[t >> 5] = ss;
    __syncthreads();
    float tot = sh[0] + sh[1] + sh[2] + sh[3];
    float inv = 1.0f / fmaxf(sqrtf(tot), 1e-12f);
    dst[t] = x0 * inv; dst[t + 128] = x1 * inv; dst[t + 256] = x2 * inv;
}

// ---------------- K2: teacher cls softmax (64 rows) ----------------
__global__ void __launch_bounds__(256) k_tcls(const float* __restrict__ tcls,
                                              const float* __restrict__ center,
                                              const int* __restrict__ ep) {
    __shared__ float sh[8];
    int row = blockIdx.x, tid = threadIdx.x;
    float it = 1.0f / read_temp(ep);
    const float4* xp = (const float4*)(tcls + (size_t)row * DIM);
    const float4* cp = (const float4*)center;
    float y[16];
#pragma unroll
    for (int k = 0; k < 4; k++) {
        float4 x = xp[tid + 256 * k], c = cp[tid + 256 * k];
        y[4*k+0] = (x.x - c.x) * it; y[4*k+1] = (x.y - c.y) * it;
        y[4*k+2] = (x.z - c.z) * it; y[4*k+3] = (x.w - c.w) * it;
    }
    float mx = -3.4e38f;
#pragma unroll
    for (int k = 0; k < 16; k++) mx = fmaxf(mx, y[k]);
    mx = blkMax(mx, sh);
    float se = 0.f;
#pragma unroll
    for (int k = 0; k < 16; k++) { y[k] = __expf(y[k] - mx); se += y[k]; }
    se = blkSum(se, sh);
    float inv = 1.0f / se;
    float4* op = (float4*)(g_tcls + (size_t)row * DIM);
#pragma unroll
    for (int k = 0; k < 4; k++)
        op[tid + 256 * k] = make_float4(y[4*k+0]*inv, y[4*k+1]*inv, y[4*k+2]*inv, y[4*k+3]*inv);
}

// ---------------- K3: teacher region softmax -> bf16 probs ----------------
__global__ void __launch_bounds__(256) k_prob(const float* __restrict__ treg,
                                              const float* __restrict__ cgrid,
                                              const int* __restrict__ ep) {
    __shared__ float sh[8];
    int row = blockIdx.x, tid = threadIdx.x;
    float it = 1.0f / read_temp(ep);
    const float4* xp = (const float4*)(treg + (size_t)row * DIM);
    const float4* cp = (const float4*)cgrid;
    float y[16];
#pragma unroll
    for (int k = 0; k < 4; k++) {
        float4 x = xp[tid + 256 * k], c = cp[tid + 256 * k];
        y[4*k+0] = (x.x - c.x) * it; y[4*k+1] = (x.y - c.y) * it;
        y[4*k+2] = (x.z - c.z) * it; y[4*k+3] = (x.w - c.w) * it;
    }
    float mx = -3.4e38f;
#pragma unroll
    for (int k = 0; k < 16; k++) mx = fmaxf(mx, y[k]);
    mx = blkMax(mx, sh);
    float se = 0.f;
#pragma unroll
    for (int k = 0; k < 16; k++) { y[k] = __expf(y[k] - mx); se += y[k]; }
    se = blkSum(se, sh);
    float inv = 1.0f / se;
    uint2* op = g_tprob + (size_t)row * (DIM / 4);
#pragma unroll
    for (int k = 0; k < 4; k++) {
        __nv_bfloat162 h0 = __float22bfloat162_rn(make_float2(y[4*k+0]*inv, y[4*k+1]*inv));
        __nv_bfloat162 h1 = __float22bfloat162_rn(make_float2(y[4*k+2]*inv, y[4*k+3]*inv));
        uint2 u;
        u.x = *reinterpret_cast<unsigned int*>(&h0);
        u.y = *reinterpret_cast<unsigned int*>(&h1);
        op[tid + 256 * k] = u;
    }
}

// ---------------- K4: cosine-sim argmax, smem-tiled exact GEMM ----------------
// 960 blocks: [0,448) global pairs (28s x 196n per block, 7 s-tiles),
//             [448,960) local pairs (36s x 196n per block).
__global__ void __launch_bounds__(256) k_sim() {
    __shared__ __align__(16) float As[16][36];
    __shared__ float Bs[16][196];
    __shared__ unsigned long long keys[36];
    int gb = blockIdx.x, t = threadIdx.x;
    int p, b, s0, Stile, S;
    if (gb < 448) {
        int pb = gb / 7; s0 = (gb % 7) * 28;
        p = (pb < 32) ? 0 : 9; b = pb & 31; Stile = 28; S = NGLOB;
    } else {
        int lb = gb - 448; int lp = lb >> 5; b = lb & 31;
        p = (lp < 8) ? (1 + lp) : (10 + (lp - 8));
        s0 = 0; Stile = 36; S = NLOC;
    }
    int i = (p < 9) ? 0 : 1;
    int j = (p < 9) ? ((p == 0) ? 1 : p + 1) : ((p == 9) ? 0 : p - 8);
    int sbase = c_SOFF[j] + b * S + s0;
    int trow0 = i * (NB * NGLOB) + b * NGLOB;

    int nthr = Stile * 7;           // 196 or 252
    int tx = t % 28, ty = t / 28;
    bool act = t < nthr;
    int nA = Stile * 4;

    float acc[4][7];
#pragma unroll
    for (int r = 0; r < 4; r++)
#pragma unroll
        for (int c = 0; c < 7; c++) acc[r][c] = 0.f;

    const float4* sf = (const float4*)g_sfea;
    const float4* tf = (const float4*)g_tfea;

    for (int ch = 0; ch < 24; ch++) {
        for (int q = t; q < nA; q += 256) {
            int row = q >> 2, kq = q & 3;
            float4 v = sf[(size_t)(sbase + row) * 96 + ch * 4 + kq];
            As[kq*4+0][row] = v.x; As[kq*4+1][row] = v.y;
            As[kq*4+2][row] = v.z; As[kq*4+3][row] = v.w;
        }
        for (int q = t; q < 784; q += 256) {
            int row = q >> 2, kq = q & 3;
            float4 v = tf[(size_t)(trow0 + row) * 96 + ch * 4 + kq];
            Bs[kq*4+0][row] = v.x; Bs[kq*4+1][row] = v.y;
            Bs[kq*4+2][row] = v.z; Bs[kq*4+3][row] = v.w;
        }
        __syncthreads();
        if (act) {
#pragma unroll
            for (int kk = 0; kk < 16; kk++) {
                float4 a = *(const float4*)&As[kk][ty * 4];
                float bv[7];
#pragma unroll
                for (int c = 0; c < 7; c++) bv[c] = Bs[kk][tx + 28 * c];
#pragma unroll
                for (int c = 0; c < 7; c++) {
                    acc[0][c] += a.x * bv[c];
                    acc[1][c] += a.y * bv[c];
                    acc[2][c] += a.z * bv[c];
                    acc[3][c] += a.w * bv[c];
                }
            }
        }
        __syncthreads();
    }

    if (t < Stile) keys[t] = 0ull;
    __syncthreads();
    if (act) {
#pragma unroll
        for (int r = 0; r < 4; r++) {
            unsigned long long key = 0ull;
#pragma unroll
            for (int c = 0; c < 7; c++) {
                int n = tx + 28 * c;
                unsigned long long k2 =
                    ((unsigned long long)ordf(acc[r][c]) << 32) | (unsigned)(0xFFFF - n);
                if (k2 > key) key = k2;
            }
            atomicMax(&keys[ty * 4 + r], key);
        }
    }
    __syncthreads();
    if (t < Stile)
        atomicMax(&g_best[c_POFF[p] + b * S + s0 + t], keys[t]);
}

// ---------------- K5: cls loss (18 pairs x 32 b) ----------------
__global__ void __launch_bounds__(256) k_cls(const float* __restrict__ scls) {
    __shared__ float sh[8];
    int p = blockIdx.x, b = blockIdx.y, tid = threadIdx.x;
    int i = (p < 9) ? 0 : 1;
    int j = (p < 9) ? ((p == 0) ? 1 : p + 1) : ((p == 9) ? 0 : p - 8);
    const float4* vp = (const float4*)(scls + (size_t)(j * NB + b) * DIM);
    const float4* qp = (const float4*)(g_tcls + (size_t)(i * NB + b) * DIM);
    float v[16], q[16];
#pragma unroll
    for (int k = 0; k < 4; k++) {
        float4 a = vp[tid + 256 * k], c = qp[tid + 256 * k];
        v[4*k+0] = a.x * 10.f; v[4*k+1] = a.y * 10.f; v[4*k+2] = a.z * 10.f; v[4*k+3] = a.w * 10.f;
        q[4*k+0] = c.x; q[4*k+1] = c.y; q[4*k+2] = c.z; q[4*k+3] = c.w;
    }
    float mx = -3.4e38f;
#pragma unroll
    for (int k = 0; k < 16; k++) mx = fmaxf(mx, v[k]);
    mx = blkMax(mx, sh);
    float se = 0.f, qv = 0.f;
#pragma unroll
    for (int k = 0; k < 16; k++) { se += __expf(v[k] - mx); qv += q[k] * v[k]; }
    se = blkSum(se, sh);
    qv = blkSum(qv, sh);
    if (tid == 0) {
        float lse = mx + logf(se);
        atomicAdd(&g_acc, (double)(lse - qv) * (0.5 / (32.0 * 18.0)));
    }
}

// ---------------- K6: region loss (lse + bf16 prob dots, no exp) ----------------
__global__ void __launch_bounds__(256) k_region(const float* __restrict__ sreg) {
    __shared__ float sh[8];
    int row = blockIdx.x, tid = threadIdx.x;
    int j, b, s;
    if (row < 12544) { j = row / 6272; int r = row - j * 6272; b = r / NGLOB; s = r - b * NGLOB; }
    else { int lr = row - 12544; j = 2 + lr / 1152; int r = lr % 1152; b = r / NLOC; s = r - b * NLOC; }
    int S = (j < 2) ? NGLOB : NLOC;

    const float4* sp = (const float4*)(sreg + (size_t)row * DIM);
    float4 v[4];
#pragma unroll
    for (int k = 0; k < 4; k++) {
        float4 t = sp[tid + 256 * k];
        v[k] = make_float4(t.x * 10.f, t.y * 10.f, t.z * 10.f, t.w * 10.f);
    }
    float mx = -3.4e38f;
#pragma unroll
    for (int k = 0; k < 4; k++)
        mx = fmaxf(mx, fmaxf(fmaxf(v[k].x, v[k].y), fmaxf(v[k].z, v[k].w)));
    mx = blkMax(mx, sh);
    float se = 0.f;
#pragma unroll
    for (int k = 0; k < 4; k++)
        se += __expf(v[k].x - mx) + __expf(v[k].y - mx) + __expf(v[k].z - mx) + __expf(v[k].w - mx);
    se = blkSum(se, sh);
    float lse = mx + logf(se);

    int np, is0, is1;
    if (j == 0) { is0 = 1; is1 = 1; np = 1; }
    else if (j == 1) { is0 = 0; is1 = 0; np = 1; }
    else { is0 = 0; is1 = 1; np = 2; }

    float dotsum = 0.f;
    for (int qq = 0; qq < np; qq++) {
        int i = (qq == 0) ? is0 : is1;
        int p = (i == 0) ? ((j == 1) ? 0 : (j - 1)) : ((j == 0) ? 9 : (j + 8));
        unsigned long long key = g_best[c_POFF[p] + b * S + s];
        int n = 0xFFFF - (int)(key & 0xFFFFull);
        int trow = i * 6272 + b * NGLOB + n;
        const uint2* pp = g_tprob + (size_t)trow * (DIM / 4);
        float part = 0.f;
#pragma unroll
        for (int k = 0; k < 4; k++) {
            uint2 u = pp[tid + 256 * k];
            __nv_bfloat162 h0 = *reinterpret_cast<__nv_bfloat162*>(&u.x);
            __nv_bfloat162 h1 = *reinterpret_cast<__nv_bfloat162*>(&u.y);
            float2 f0 = __bfloat1622float2(h0);
            float2 f1 = __bfloat1622float2(h1);
            part += f0.x * v[k].x + f0.y * v[k].y + f1.x * v[k].z + f1.y * v[k].w;
        }
        part = blkSum(part, sh);
        dotsum += part;
    }
    if (tid == 0) {
        double contrib = ((double)np * (double)lse - (double)dotsum)
                       * (0.5 / ((double)S * 32.0 * 18.0));
        atomicAdd(&g_acc, contrib);
    }
}

// ---------------- K7: finalize ----------------
__global__ void k_fin(float* out) { out[0] = (float)g_acc; }

// ---------------- launch ----------------
extern "C" void kernel_launch(void* const* d_in, const int* in_sizes, int n_in,
                              void* d_out, int out_size) {
    (void)in_sizes; (void)n_in; (void)out_size;
    const float* s_cls  = (const float*)d_in[0];
    const float* s_reg  = (const float*)d_in[1];
    const float* s_fea  = (const float*)d_in[2];
    const float* t_cls  = (const float*)d_in[3];
    const float* t_reg  = (const float*)d_in[4];
    const float* t_fea  = (const float*)d_in[5];
    const float* center = (const float*)d_in[6];
    const float* cgrid  = (const float*)d_in[7];
    const int*   ep     = (const int*)d_in[8];

    k_init<<<121, 256>>>();
    k_norm<<<SROWS + TROWS, 128>>>(s_fea, t_fea);
    k_tcls<<<64, 256>>>(t_cls, center, ep);
    k_prob<<<TROWS, 256>>>(t_reg, cgrid, ep);
    k_sim<<<960, 256>>>();
    k_cls<<<dim3(18, NB), 256>>>(s_cls);
    k_region<<<SROWS, 256>>>(s_reg);
    k_fin<<<1, 1>>>((float*)d_out);
}

// round 3
// speedup vs baseline: 3.2059x; 1.1219x over previous
#include <cuda_runtime.h>
#include <cuda_bf16.h>

#define NB     32
#define DIM    4096
#define FDIM   384
#define NGLOB  196
#define NLOC   36
#define SROWS  21760
#define TROWS  12544
#define TOTIND 30976

// ---------------- scratch (device globals; no allocations) ----------------
static __device__ float g_sfea[(size_t)SROWS * FDIM];   // normalized student feats (tf32-rounded)
static __device__ float g_tfea[(size_t)TROWS * FDIM];   // normalized teacher feats (tf32-rounded)
static __device__ float g_tcls[64 * DIM];               // teacher cls softmax
static __device__ uint2 g_tprob[(size_t)TROWS * DIM / 4]; // teacher region softmax, bf16 x4 packed
static __device__ unsigned long long g_best[TOTIND];    // packed argmax (val<<32 | 0xFFFF-n)
static __device__ double g_acc;

// pair p: p in [0,9) -> i=0, j = (p==0?1:p+1) ; p in [9,18) -> i=1, j = (p==9?0:p-8)
__constant__ int c_POFF[18] = {0,6272,7424,8576,9728,10880,12032,13184,14336,
                               15488,21760,22912,24064,25216,26368,27520,28672,29824};
__constant__ int c_SOFF[10] = {0,6272,12544,13696,14848,16000,17152,18304,19456,20608};

// ---------------- helpers ----------------
__device__ __forceinline__ float read_temp(const int* ep) {
    int e = *ep;
    if (e < 0 || e > 100000) e = (int)__int_as_float(e);
    return (e < 30) ? (0.04f + 0.03f * (float)e * (1.0f / 29.0f)) : 0.07f;
}
__device__ __forceinline__ float warpRedSum(float v) {
#pragma unroll
    for (int o = 16; o > 0; o >>= 1) v += __shfl_xor_sync(0xffffffffu, v, o);
    return v;
}
__device__ __forceinline__ float warpRedMax(float v) {
#pragma unroll
    for (int o = 16; o > 0; o >>= 1) v = fmaxf(v, __shfl_xor_sync(0xffffffffu, v, o));
    return v;
}
__device__ __forceinline__ float blkSum(float v, float* sh) {
    v = warpRedSum(v);
    if ((threadIdx.x & 31) == 0) sh[threadIdx.x >> 5] = v;
    __syncthreads();
    float r = sh[0]+sh[1]+sh[2]+sh[3]+sh[4]+sh[5]+sh[6]+sh[7];
    __syncthreads();
    return r;
}
__device__ __forceinline__ float blkMax(float v, float* sh) {
    v = warpRedMax(v);
    if ((threadIdx.x & 31) == 0) sh[threadIdx.x >> 5] = v;
    __syncthreads();
    float r = fmaxf(fmaxf(fmaxf(sh[0],sh[1]),fmaxf(sh[2],sh[3])),
                    fmaxf(fmaxf(sh[4],sh[5]),fmaxf(sh[6],sh[7])));
    __syncthreads();
    return r;
}
__device__ __forceinline__ unsigned int ordf(float f) {
    unsigned int u = __float_as_uint(f);
    return (u & 0x80000000u) ? ~u : (u | 0x80000000u);
}
__device__ __forceinline__ float tf32r(float x) {
    unsigned u;
    asm("cvt.rna.tf32.f32 %0, %1;" : "=r"(u) : "f"(x));
    return __uint_as_float(u);
}

// ---------------- K0: init ----------------
__global__ void k_init() {
    int i = blockIdx.x * blockDim.x + threadIdx.x;
    if (i == 0) g_acc = 0.0;
    if (i < TOTIND) g_best[i] = 0ull;
}

// ---------------- K1: L2-normalize feats (emit tf32-rounded) ----------------
__global__ void __launch_bounds__(128) k_norm(const float* __restrict__ sf,
                                              const float* __restrict__ tf) {
    __shared__ float sh[4];
    int row = blockIdx.x;
    const float* src; float* dst;
    if (row < SROWS) { src = sf + (size_t)row * FDIM; dst = g_sfea + (size_t)row * FDIM; }
    else { int r = row - SROWS; src = tf + (size_t)r * FDIM; dst = g_tfea + (size_t)r * FDIM; }
    int t = threadIdx.x;
    float x0 = src[t], x1 = src[t + 128], x2 = src[t + 256];
    float ss = x0*x0 + x1*x1 + x2*x2;
    ss = warpRedSum(ss);
    if ((t & 31) == 0) sh[t >> 5] = ss;
    __syncthreads();
    float tot = sh[0] + sh[1] + sh[2] + sh[3];
    float inv = 1.0f / fmaxf(sqrtf(tot), 1e-12f);
    dst[t] = tf32r(x0 * inv); dst[t + 128] = tf32r(x1 * inv); dst[t + 256] = tf32r(x2 * inv);
}

// ---------------- K2: teacher cls softmax (64 rows) ----------------
__global__ void __launch_bounds__(256) k_tcls(const float* __restrict__ tcls,
                                              const float* __restrict__ center,
                                              const int* __restrict__ ep) {
    __shared__ float sh[8];
    int row = blockIdx.x, tid = threadIdx.x;
    float it = 1.0f / read_temp(ep);
    const float4* xp = (const float4*)(tcls + (size_t)row * DIM);
    const float4* cp = (const float4*)center;
    float y[16];
#pragma unroll
    for (int k = 0; k < 4; k++) {
        float4 x = xp[tid + 256 * k], c = cp[tid + 256 * k];
        y[4*k+0] = (x.x - c.x) * it; y[4*k+1] = (x.y - c.y) * it;
        y[4*k+2] = (x.z - c.z) * it; y[4*k+3] = (x.w - c.w) * it;
    }
    float mx = -3.4e38f;
#pragma unroll
    for (int k = 0; k < 16; k++) mx = fmaxf(mx, y[k]);
    mx = blkMax(mx, sh);
    float se = 0.f;
#pragma unroll
    for (int k = 0; k < 16; k++) { y[k] = __expf(y[k] - mx); se += y[k]; }
    se = blkSum(se, sh);
    float inv = 1.0f / se;
    float4* op = (float4*)(g_tcls + (size_t)row * DIM);
#pragma unroll
    for (int k = 0; k < 4; k++)
        op[tid + 256 * k] = make_float4(y[4*k+0]*inv, y[4*k+1]*inv, y[4*k+2]*inv, y[4*k+3]*inv);
}

// ---------------- K3: teacher region softmax -> bf16 probs ----------------
__global__ void __launch_bounds__(256) k_prob(const float* __restrict__ treg,
                                              const float* __restrict__ cgrid,
                                              const int* __restrict__ ep) {
    __shared__ float sh[8];
    int row = blockIdx.x, tid = threadIdx.x;
    float it = 1.0f / read_temp(ep);
    const float4* xp = (const float4*)(treg + (size_t)row * DIM);
    const float4* cp = (const float4*)cgrid;
    float y[16];
#pragma unroll
    for (int k = 0; k < 4; k++) {
        float4 x = xp[tid + 256 * k], c = cp[tid + 256 * k];
        y[4*k+0] = (x.x - c.x) * it; y[4*k+1] = (x.y - c.y) * it;
        y[4*k+2] = (x.z - c.z) * it; y[4*k+3] = (x.w - c.w) * it;
    }
    float mx = -3.4e38f;
#pragma unroll
    for (int k = 0; k < 16; k++) mx = fmaxf(mx, y[k]);
    mx = blkMax(mx, sh);
    float se = 0.f;
#pragma unroll
    for (int k = 0; k < 16; k++) { y[k] = __expf(y[k] - mx); se += y[k]; }
    se = blkSum(se, sh);
    float inv = 1.0f / se;
    uint2* op = g_tprob + (size_t)row * (DIM / 4);
#pragma unroll
    for (int k = 0; k < 4; k++) {
        __nv_bfloat162 h0 = __float22bfloat162_rn(make_float2(y[4*k+0]*inv, y[4*k+1]*inv));
        __nv_bfloat162 h1 = __float22bfloat162_rn(make_float2(y[4*k+2]*inv, y[4*k+3]*inv));
        uint2 u;
        u.x = *reinterpret_cast<unsigned int*>(&h0);
        u.y = *reinterpret_cast<unsigned int*>(&h1);
        op[tid + 256 * k] = u;
    }
}

// ---------------- K4: cosine-sim argmax via tf32 mma.sync ----------------
// Grid 512: blockIdx.x = mt(3b) | b(5b) | i(1b). Per (i,b): A = 484 gathered
// student rows (196 global + 8*36 local), B = 196 teacher rows, K=384.
// Block tile 64x208 (8 warps: 4M x 2N, warp tile 16x104 = 13 n8-tiles).
__device__ __forceinline__ int srow_of(int i, int b, int r) {
    if (r >= 484) r = 483;
    if (r < 196) {
        int j = (i == 0) ? 1 : 0;
        return c_SOFF[j] + b * NGLOB + r;
    }
    int lr = r - 196;
    int lj = lr / 36;
    int s = lr - lj * 36;
    return c_SOFF[lj + 2] + b * NLOC + s;
}

__global__ void __launch_bounds__(256) k_sim() {
    __shared__ __align__(16) float As[64][20];
    __shared__ float Bs[16][216];

    int t = threadIdx.x;
    int mt = blockIdx.x & 7;
    int b  = (blockIdx.x >> 3) & 31;
    int i  = blockIdx.x >> 8;
    int trow0 = i * 6272 + b * NGLOB;

    int lane = t & 31, wid = t >> 5;
    int warpM = wid >> 1, warpN = wid & 1;
    int g = lane >> 2, tig = lane & 3;
    int mb = warpM * 16, nb = warpN * 104;

    float acc[13][4];
#pragma unroll
    for (int q = 0; q < 13; q++) {
        acc[q][0] = 0.f; acc[q][1] = 0.f; acc[q][2] = 0.f; acc[q][3] = 0.f;
    }

    const float4* sf = (const float4*)g_sfea;
    const float4* tf = (const float4*)g_tfea;

    // Precompute this thread's global A row for loading
    int arow = t >> 2, akq = t & 3;
    size_t a_src = (size_t)srow_of(i, b, mt * 64 + arow) * 96;

    for (int ch = 0; ch < 24; ch++) {
        // load A: 64 rows x 16 k
        {
            float4 v = sf[a_src + ch * 4 + akq];
            *(float4*)&As[arow][akq * 4] = v;
        }
        // load B transposed: Bs[k][n], 208 n-rows (clamped) x 16 k
        for (int u = t; u < 832; u += 256) {
            int n = u >> 2, kq = u & 3;
            int gn = (n > 195) ? 195 : n;
            float4 v = tf[(size_t)(trow0 + gn) * 96 + ch * 4 + kq];
            Bs[kq*4+0][n] = v.x; Bs[kq*4+1][n] = v.y;
            Bs[kq*4+2][n] = v.z; Bs[kq*4+3][n] = v.w;
        }
        __syncthreads();
#pragma unroll
        for (int ks = 0; ks < 2; ks++) {
            int kof = ks * 8;
            unsigned a0 = __float_as_uint(As[mb + g    ][kof + tig    ]);
            unsigned a1 = __float_as_uint(As[mb + g + 8][kof + tig    ]);
            unsigned a2 = __float_as_uint(As[mb + g    ][kof + tig + 4]);
            unsigned a3 = __float_as_uint(As[mb + g + 8][kof + tig + 4]);
#pragma unroll
            for (int q = 0; q < 13; q++) {
                unsigned b0 = __float_as_uint(Bs[kof + tig    ][nb + q * 8 + g]);
                unsigned b1 = __float_as_uint(Bs[kof + tig + 4][nb + q * 8 + g]);
                asm volatile(
                    "mma.sync.aligned.m16n8k8.row.col.f32.tf32.tf32.f32 "
                    "{%0,%1,%2,%3}, {%4,%5,%6,%7}, {%8,%9}, {%0,%1,%2,%3};\n"
                    : "+f"(acc[q][0]), "+f"(acc[q][1]), "+f"(acc[q][2]), "+f"(acc[q][3])
                    : "r"(a0), "r"(a1), "r"(a2), "r"(a3), "r"(b0), "r"(b1));
            }
        }
        __syncthreads();
    }

    // epilogue: per-row packed argmax keys
    unsigned long long key0 = 0ull, key1 = 0ull;  // rows g, g+8
#pragma unroll
    for (int q = 0; q < 13; q++) {
        int n0 = nb + q * 8 + 2 * tig;
#pragma unroll
        for (int d = 0; d < 2; d++) {
            int n = n0 + d;
            if (n < NGLOB) {
                unsigned long long kk0 =
                    ((unsigned long long)ordf(acc[q][d]) << 32) | (unsigned)(0xFFFF - n);
                if (kk0 > key0) key0 = kk0;
                unsigned long long kk1 =
                    ((unsigned long long)ordf(acc[q][2 + d]) << 32) | (unsigned)(0xFFFF - n);
                if (kk1 > key1) key1 = kk1;
            }
        }
    }
#pragma unroll
    for (int m = 1; m < 4; m <<= 1) {
        unsigned long long o0 = __shfl_xor_sync(0xffffffffu, key0, m);
        if (o0 > key0) key0 = o0;
        unsigned long long o1 = __shfl_xor_sync(0xffffffffu, key1, m);
        if (o1 > key1) key1 = o1;
    }
    if (tig == 0) {
#pragma unroll
        for (int d = 0; d < 2; d++) {
            int r = mt * 64 + mb + g + d * 8;
            unsigned long long key = d ? key1 : key0;
            if (r < 484) {
                int p, s, S;
                if (r < 196) { p = (i == 0) ? 0 : 9; s = r; S = NGLOB; }
                else {
                    int lr = r - 196;
                    int lj = lr / 36;
                    s = lr - lj * 36; S = NLOC;
                    p = (i == 0) ? (lj + 1) : (lj + 10);
                }
                atomicMax(&g_best[c_POFF[p] + b * S + s], key);
            }
        }
    }
}

// ---------------- K5: cls loss (18 pairs x 32 b) ----------------
__global__ void __launch_bounds__(256) k_cls(const float* __restrict__ scls) {
    __shared__ float sh[8];
    int p = blockIdx.x, b = blockIdx.y, tid = threadIdx.x;
    int i = (p < 9) ? 0 : 1;
    int j = (p < 9) ? ((p == 0) ? 1 : p + 1) : ((p == 9) ? 0 : p - 8);
    const float4* vp = (const float4*)(scls + (size_t)(j * NB + b) * DIM);
    const float4* qp = (const float4*)(g_tcls + (size_t)(i * NB + b) * DIM);
    float v[16], q[16];
#pragma unroll
    for (int k = 0; k < 4; k++) {
        float4 a = vp[tid + 256 * k], c = qp[tid + 256 * k];
        v[4*k+0] = a.x * 10.f; v[4*k+1] = a.y * 10.f; v[4*k+2] = a.z * 10.f; v[4*k+3] = a.w * 10.f;
        q[4*k+0] = c.x; q[4*k+1] = c.y; q[4*k+2] = c.z; q[4*k+3] = c.w;
    }
    float mx = -3.4e38f;
#pragma unroll
    for (int k = 0; k < 16; k++) mx = fmaxf(mx, v[k]);
    mx = blkMax(mx, sh);
    float se = 0.f, qv = 0.f;
#pragma unroll
    for (int k = 0; k < 16; k++) { se += __expf(v[k] - mx); qv += q[k] * v[k]; }
    se = blkSum(se, sh);
    qv = blkSum(qv, sh);
    if (tid == 0) {
        float lse = mx + logf(se);
        atomicAdd(&g_acc, (double)(lse - qv) * (0.5 / (32.0 * 18.0)));
    }
}

// ---------------- K6: region loss (lse + bf16 prob dots, no exp) ----------------
__global__ void __launch_bounds__(256) k_region(const float* __restrict__ sreg) {
    __shared__ float sh[8];
    int row = blockIdx.x, tid = threadIdx.x;
    int j, b, s;
    if (row < 12544) { j = row / 6272; int r = row - j * 6272; b = r / NGLOB; s = r - b * NGLOB; }
    else { int lr = row - 12544; j = 2 + lr / 1152; int r = lr % 1152; b = r / NLOC; s = r - b * NLOC; }
    int S = (j < 2) ? NGLOB : NLOC;

    const float4* sp = (const float4*)(sreg + (size_t)row * DIM);
    float4 v[4];
#pragma unroll
    for (int k = 0; k < 4; k++) {
        float4 t = sp[tid + 256 * k];
        v[k] = make_float4(t.x * 10.f, t.y * 10.f, t.z * 10.f, t.w * 10.f);
    }
    float mx = -3.4e38f;
#pragma unroll
    for (int k = 0; k < 4; k++)
        mx = fmaxf(mx, fmaxf(fmaxf(v[k].x, v[k].y), fmaxf(v[k].z, v[k].w)));
    mx = blkMax(mx, sh);
    float se = 0.f;
#pragma unroll
    for (int k = 0; k < 4; k++)
        se += __expf(v[k].x - mx) + __expf(v[k].y - mx) + __expf(v[k].z - mx) + __expf(v[k].w - mx);
    se = blkSum(se, sh);
    float lse = mx + logf(se);

    int np, is0, is1;
    if (j == 0) { is0 = 1; is1 = 1; np = 1; }
    else if (j == 1) { is0 = 0; is1 = 0; np = 1; }
    else { is0 = 0; is1 = 1; np = 2; }

    float dotsum = 0.f;
    for (int qq = 0; qq < np; qq++) {
        int i = (qq == 0) ? is0 : is1;
        int p = (i == 0) ? ((j == 1) ? 0 : (j - 1)) : ((j == 0) ? 9 : (j + 8));
        unsigned long long key = g_best[c_POFF[p] + b * S + s];
        int n = 0xFFFF - (int)(key & 0xFFFFull);
        int trow = i * 6272 + b * NGLOB + n;
        const uint2* pp = g_tprob + (size_t)trow * (DIM / 4);
        float part = 0.f;
#pragma unroll
        for (int k = 0; k < 4; k++) {
            uint2 u = pp[tid + 256 * k];
            __nv_bfloat162 h0 = *reinterpret_cast<__nv_bfloat162*>(&u.x);
            __nv_bfloat162 h1 = *reinterpret_cast<__nv_bfloat162*>(&u.y);
            float2 f0 = __bfloat1622float2(h0);
            float2 f1 = __bfloat1622float2(h1);
            part += f0.x * v[k].x + f0.y * v[k].y + f1.x * v[k].z + f1.y * v[k].w;
        }
        part = blkSum(part, sh);
        dotsum += part;
    }
    if (tid == 0) {
        double contrib = ((double)np * (double)lse - (double)dotsum)
                       * (0.5 / ((double)S * 32.0 * 18.0));
        atomicAdd(&g_acc, contrib);
    }
}

// ---------------- K7: finalize ----------------
__global__ void k_fin(float* out) { out[0] = (float)g_acc; }

// ---------------- launch ----------------
extern "C" void kernel_launch(void* const* d_in, const int* in_sizes, int n_in,
                              void* d_out, int out_size) {
    (void)in_sizes; (void)n_in; (void)out_size;
    const float* s_cls  = (const float*)d_in[0];
    const float* s_reg  = (const float*)d_in[1];
    const float* s_fea  = (const float*)d_in[2];
    const float* t_cls  = (const float*)d_in[3];
    const float* t_reg  = (const float*)d_in[4];
    const float* t_fea  = (const float*)d_in[5];
    const float* center = (const float*)d_in[6];
    const float* cgrid  = (const float*)d_in[7];
    const int*   ep     = (const int*)d_in[8];

    k_init<<<121, 256>>>();
    k_norm<<<SROWS + TROWS, 128>>>(s_fea, t_fea);
    k_tcls<<<64, 256>>>(t_cls, center, ep);
    k_prob<<<TROWS, 256>>>(t_reg, cgrid, ep);
    k_sim<<<512, 256>>>();
    k_cls<<<dim3(18, NB), 256>>>(s_cls);
    k_region<<<SROWS, 256>>>(s_reg);
    k_fin<<<1, 1>>>((float*)d_out);
}

// round 4
// speedup vs baseline: 4.2517x; 1.3262x over previous
#include <cuda_runtime.h>
#include <cuda_bf16.h>

#define NB     32
#define DIM    4096
#define FDIM   384
#define NGLOB  196
#define NLOC   36
#define SROWS  21760
#define TROWS  12544
#define TOTIND 30976

// ---------------- scratch (device globals; no allocations) ----------------
static __device__ float g_sfea[(size_t)SROWS * FDIM];   // normalized student feats (tf32-rounded)
static __device__ float g_tfea[(size_t)TROWS * FDIM];   // normalized teacher feats (tf32-rounded)
static __device__ float g_tcls[64 * DIM];               // teacher cls softmax
static __device__ uint2 g_tprob[(size_t)TROWS * DIM / 4]; // teacher region softmax, bf16 x4 packed
static __device__ unsigned long long g_best[TOTIND];    // packed argmax (val<<32 | 0xFFFF-n)
static __device__ double g_acc;

__constant__ int c_POFF[18] = {0,6272,7424,8576,9728,10880,12032,13184,14336,
                               15488,21760,22912,24064,25216,26368,27520,28672,29824};
__constant__ int c_SOFF[10] = {0,6272,12544,13696,14848,16000,17152,18304,19456,20608};

// ---------------- helpers ----------------
__device__ __forceinline__ float read_temp(const int* ep) {
    int e = *ep;
    if (e < 0 || e > 100000) e = (int)__int_as_float(e);
    return (e < 30) ? (0.04f + 0.03f * (float)e * (1.0f / 29.0f)) : 0.07f;
}
__device__ __forceinline__ float warpRedSum(float v) {
#pragma unroll
    for (int o = 16; o > 0; o >>= 1) v += __shfl_xor_sync(0xffffffffu, v, o);
    return v;
}
__device__ __forceinline__ float warpRedMax(float v) {
#pragma unroll
    for (int o = 16; o > 0; o >>= 1) v = fmaxf(v, __shfl_xor_sync(0xffffffffu, v, o));
    return v;
}
__device__ __forceinline__ float blkSum(float v, float* sh) {
    v = warpRedSum(v);
    if ((threadIdx.x & 31) == 0) sh[threadIdx.x >> 5] = v;
    __syncthreads();
    float r = sh[0]+sh[1]+sh[2]+sh[3]+sh[4]+sh[5]+sh[6]+sh[7];
    __syncthreads();
    return r;
}
__device__ __forceinline__ float blkMax(float v, float* sh) {
    v = warpRedMax(v);
    if ((threadIdx.x & 31) == 0) sh[threadIdx.x >> 5] = v;
    __syncthreads();
    float r = fmaxf(fmaxf(fmaxf(sh[0],sh[1]),fmaxf(sh[2],sh[3])),
                    fmaxf(fmaxf(sh[4],sh[5]),fmaxf(sh[6],sh[7])));
    __syncthreads();
    return r;
}
__device__ __forceinline__ unsigned int ordf(float f) {
    unsigned int u = __float_as_uint(f);
    return (u & 0x80000000u) ? ~u : (u | 0x80000000u);
}
__device__ __forceinline__ float tf32r(float x) {
    unsigned u;
    asm("cvt.rna.tf32.f32 %0, %1;" : "=r"(u) : "f"(x));
    return __uint_as_float(u);
}
__device__ __forceinline__ unsigned smem_u32(const void* p) {
    return (unsigned)__cvta_generic_to_shared(p);
}
#define CP_ASYNC16(dst, src) \
    asm volatile("cp.async.ca.shared.global [%0], [%1], 16;" :: "r"(dst), "l"(src))
#define CP_COMMIT asm volatile("cp.async.commit_group;")

// ---------------- K0: init ----------------
__global__ void k_init() {
    int i = blockIdx.x * blockDim.x + threadIdx.x;
    if (i == 0) g_acc = 0.0;
    if (i < TOTIND) g_best[i] = 0ull;
}

// ---------------- K1: L2-normalize feats (emit tf32-rounded) ----------------
__global__ void __launch_bounds__(128) k_norm(const float* __restrict__ sf,
                                              const float* __restrict__ tf) {
    __shared__ float sh[4];
    int row = blockIdx.x;
    const float* src; float* dst;
    if (row < SROWS) { src = sf + (size_t)row * FDIM; dst = g_sfea + (size_t)row * FDIM; }
    else { int r = row - SROWS; src = tf + (size_t)r * FDIM; dst = g_tfea + (size_t)r * FDIM; }
    int t = threadIdx.x;
    float x0 = __ldcs(src + t), x1 = __ldcs(src + t + 128), x2 = __ldcs(src + t + 256);
    float ss = x0*x0 + x1*x1 + x2*x2;
    ss = warpRedSum(ss);
    if ((t & 31) == 0) sh[t >> 5] = ss;
    __syncthreads();
    float tot = sh[0] + sh[1] + sh[2] + sh[3];
    float inv = 1.0f / fmaxf(sqrtf(tot), 1e-12f);
    dst[t] = tf32r(x0 * inv); dst[t + 128] = tf32r(x1 * inv); dst[t + 256] = tf32r(x2 * inv);
}

// ---------------- K2: teacher cls softmax (64 rows) ----------------
__global__ void __launch_bounds__(256) k_tcls(const float* __restrict__ tcls,
                                              const float* __restrict__ center,
                                              const int* __restrict__ ep) {
    __shared__ float sh[8];
    int row = blockIdx.x, tid = threadIdx.x;
    float it = 1.0f / read_temp(ep);
    const float4* xp = (const float4*)(tcls + (size_t)row * DIM);
    const float4* cp = (const float4*)center;
    float y[16];
#pragma unroll
    for (int k = 0; k < 4; k++) {
        float4 x = xp[tid + 256 * k], c = cp[tid + 256 * k];
        y[4*k+0] = (x.x - c.x) * it; y[4*k+1] = (x.y - c.y) * it;
        y[4*k+2] = (x.z - c.z) * it; y[4*k+3] = (x.w - c.w) * it;
    }
    float mx = -3.4e38f;
#pragma unroll
    for (int k = 0; k < 16; k++) mx = fmaxf(mx, y[k]);
    mx = blkMax(mx, sh);
    float se = 0.f;
#pragma unroll
    for (int k = 0; k < 16; k++) { y[k] = __expf(y[k] - mx); se += y[k]; }
    se = blkSum(se, sh);
    float inv = 1.0f / se;
    float4* op = (float4*)(g_tcls + (size_t)row * DIM);
#pragma unroll
    for (int k = 0; k < 4; k++)
        op[tid + 256 * k] = make_float4(y[4*k+0]*inv, y[4*k+1]*inv, y[4*k+2]*inv, y[4*k+3]*inv);
}

// ---------------- K3: teacher region softmax -> bf16 probs ----------------
__global__ void __launch_bounds__(256) k_prob(const float* __restrict__ treg,
                                              const float* __restrict__ cgrid,
                                              const int* __restrict__ ep) {
    __shared__ float sh[8];
    int row = blockIdx.x, tid = threadIdx.x;
    float it = 1.0f / read_temp(ep);
    const float4* xp = (const float4*)(treg + (size_t)row * DIM);
    const float4* cp = (const float4*)cgrid;
    float y[16];
#pragma unroll
    for (int k = 0; k < 4; k++) {
        float4 x = __ldcs(xp + tid + 256 * k);
        float4 c = cp[tid + 256 * k];
        y[4*k+0] = (x.x - c.x) * it; y[4*k+1] = (x.y - c.y) * it;
        y[4*k+2] = (x.z - c.z) * it; y[4*k+3] = (x.w - c.w) * it;
    }
    float mx = -3.4e38f;
#pragma unroll
    for (int k = 0; k < 16; k++) mx = fmaxf(mx, y[k]);
    mx = blkMax(mx, sh);
    float se = 0.f;
#pragma unroll
    for (int k = 0; k < 16; k++) { y[k] = __expf(y[k] - mx); se += y[k]; }
    se = blkSum(se, sh);
    float inv = 1.0f / se;
    uint2* op = g_tprob + (size_t)row * (DIM / 4);
#pragma unroll
    for (int k = 0; k < 4; k++) {
        __nv_bfloat162 h0 = __float22bfloat162_rn(make_float2(y[4*k+0]*inv, y[4*k+1]*inv));
        __nv_bfloat162 h1 = __float22bfloat162_rn(make_float2(y[4*k+2]*inv, y[4*k+3]*inv));
        uint2 u;
        u.x = *reinterpret_cast<unsigned int*>(&h0);
        u.y = *reinterpret_cast<unsigned int*>(&h1);
        op[tid + 256 * k] = u;
    }
}

// ---------------- K4: cosine-sim argmax via tf32 mma.sync, cp.async pipelined ----------------
__device__ __forceinline__ int srow_of(int i, int b, int r) {
    if (r >= 484) r = 483;
    if (r < 196) {
        int j = (i == 0) ? 1 : 0;
        return c_SOFF[j] + b * NGLOB + r;
    }
    int lr = r - 196;
    int lj = lr / 36;
    int s = lr - lj * 36;
    return c_SOFF[lj + 2] + b * NLOC + s;
}

__global__ void __launch_bounds__(256) k_sim() {
    __shared__ __align__(16) float As[2][64][20];   // [buf][m][k], 16B-contig k-quads
    __shared__ __align__(16) float Bs[2][208][20];  // [buf][n][k]

    int t = threadIdx.x;
    int mt = blockIdx.x & 7;
    int b  = (blockIdx.x >> 3) & 31;
    int i  = blockIdx.x >> 8;
    int trow0 = i * 6272 + b * NGLOB;

    int lane = t & 31, wid = t >> 5;
    int warpM = wid >> 1, warpN = wid & 1;
    int g = lane >> 2, tig = lane & 3;
    int mb = warpM * 16, nb = warpN * 104;

    // A source: thread loads 16B of row arow, k-quad akq
    int arow = t >> 2, akq = t & 3;
    const float* a_src = g_sfea + (size_t)srow_of(i, b, mt * 64 + arow) * FDIM + akq * 4;
    unsigned sA = smem_u32(&As[0][0][0]);
    unsigned sB = smem_u32(&Bs[0][0][0]);
    unsigned dA = sA + arow * 80 + akq * 16;

    // B sources: up to 4 quads per thread (208 rows x 4 quads = 832)
    const float* b_src[4]; unsigned dB[4];
#pragma unroll
    for (int it = 0; it < 4; it++) {
        int u = t + it * 256;
        int uu = (u < 832) ? u : 831;
        int n = uu >> 2, kq = uu & 3;
        int gn = (n > 195) ? 195 : n;
        b_src[it] = g_tfea + (size_t)(trow0 + gn) * FDIM + kq * 4;
        dB[it] = sB + n * 80 + kq * 16;
    }
    bool b3 = (t < 64);  // only iteration 3 can be out of range

    float acc[13][4];
#pragma unroll
    for (int q = 0; q < 13; q++) {
        acc[q][0] = 0.f; acc[q][1] = 0.f; acc[q][2] = 0.f; acc[q][3] = 0.f;
    }

    // prefetch chunk 0 into buf 0
    {
        CP_ASYNC16(dA, a_src);
        CP_ASYNC16(dB[0], b_src[0]);
        CP_ASYNC16(dB[1], b_src[1]);
        CP_ASYNC16(dB[2], b_src[2]);
        if (b3) CP_ASYNC16(dB[3], b_src[3]);
        CP_COMMIT;
    }

    for (int ch = 0; ch < 24; ch++) {
        int buf = ch & 1;
        if (ch + 1 < 24) {
            int nb2 = (buf ^ 1) ? 1 : 0;
            unsigned aoff = nb2 * 5120u, boff = nb2 * 16640u;
            const float* ap = a_src + (ch + 1) * 16;
            CP_ASYNC16(dA + aoff, ap);
            CP_ASYNC16(dB[0] + boff, b_src[0] + (ch + 1) * 16);
            CP_ASYNC16(dB[1] + boff, b_src[1] + (ch + 1) * 16);
            CP_ASYNC16(dB[2] + boff, b_src[2] + (ch + 1) * 16);
            if (b3) CP_ASYNC16(dB[3] + boff, b_src[3] + (ch + 1) * 16);
            CP_COMMIT;
            asm volatile("cp.async.wait_group 1;");
        } else {
            asm volatile("cp.async.wait_group 0;");
        }
        __syncthreads();
#pragma unroll
        for (int ks = 0; ks < 2; ks++) {
            int kof = ks * 8;
            unsigned a0 = __float_as_uint(As[buf][mb + g    ][kof + tig    ]);
            unsigned a1 = __float_as_uint(As[buf][mb + g + 8][kof + tig    ]);
            unsigned a2 = __float_as_uint(As[buf][mb + g    ][kof + tig + 4]);
            unsigned a3 = __float_as_uint(As[buf][mb + g + 8][kof + tig + 4]);
#pragma unroll
            for (int q = 0; q < 13; q++) {
                unsigned b0 = __float_as_uint(Bs[buf][nb + q * 8 + g][kof + tig    ]);
                unsigned b1 = __float_as_uint(Bs[buf][nb + q * 8 + g][kof + tig + 4]);
                asm volatile(
                    "mma.sync.aligned.m16n8k8.row.col.f32.tf32.tf32.f32 "
                    "{%0,%1,%2,%3}, {%4,%5,%6,%7}, {%8,%9}, {%0,%1,%2,%3};\n"
                    : "+f"(acc[q][0]), "+f"(acc[q][1]), "+f"(acc[q][2]), "+f"(acc[q][3])
                    : "r"(a0), "r"(a1), "r"(a2), "r"(a3), "r"(b0), "r"(b1));
            }
        }
        __syncthreads();
    }

    // epilogue: per-row packed argmax keys
    unsigned long long key0 = 0ull, key1 = 0ull;  // rows g, g+8
#pragma unroll
    for (int q = 0; q < 13; q++) {
        int n0 = nb + q * 8 + 2 * tig;
#pragma unroll
        for (int d = 0; d < 2; d++) {
            int n = n0 + d;
            if (n < NGLOB) {
                unsigned long long kk0 =
                    ((unsigned long long)ordf(acc[q][d]) << 32) | (unsigned)(0xFFFF - n);
                if (kk0 > key0) key0 = kk0;
                unsigned long long kk1 =
                    ((unsigned long long)ordf(acc[q][2 + d]) << 32) | (unsigned)(0xFFFF - n);
                if (kk1 > key1) key1 = kk1;
            }
        }
    }
#pragma unroll
    for (int m = 1; m < 4; m <<= 1) {
        unsigned long long o0 = __shfl_xor_sync(0xffffffffu, key0, m);
        if (o0 > key0) key0 = o0;
        unsigned long long o1 = __shfl_xor_sync(0xffffffffu, key1, m);
        if (o1 > key1) key1 = o1;
    }
    if (tig == 0) {
#pragma unroll
        for (int d = 0; d < 2; d++) {
            int r = mt * 64 + mb + g + d * 8;
            unsigned long long key = d ? key1 : key0;
            if (r < 484) {
                int p, s, S;
                if (r < 196) { p = (i == 0) ? 0 : 9; s = r; S = NGLOB; }
                else {
                    int lr = r - 196;
                    int lj = lr / 36;
                    s = lr - lj * 36; S = NLOC;
                    p = (i == 0) ? (lj + 1) : (lj + 10);
                }
                atomicMax(&g_best[c_POFF[p] + b * S + s], key);
            }
        }
    }
}

// ---------------- K5: cls loss (18 pairs x 32 b) ----------------
__global__ void __launch_bounds__(256) k_cls(const float* __restrict__ scls) {
    __shared__ float sh[8];
    int p = blockIdx.x, b = blockIdx.y, tid = threadIdx.x;
    int i = (p < 9) ? 0 : 1;
    int j = (p < 9) ? ((p == 0) ? 1 : p + 1) : ((p == 9) ? 0 : p - 8);
    const float4* vp = (const float4*)(scls + (size_t)(j * NB + b) * DIM);
    const float4* qp = (const float4*)(g_tcls + (size_t)(i * NB + b) * DIM);
    float v[16], q[16];
#pragma unroll
    for (int k = 0; k < 4; k++) {
        float4 a = vp[tid + 256 * k], c = qp[tid + 256 * k];
        v[4*k+0] = a.x * 10.f; v[4*k+1] = a.y * 10.f; v[4*k+2] = a.z * 10.f; v[4*k+3] = a.w * 10.f;
        q[4*k+0] = c.x; q[4*k+1] = c.y; q[4*k+2] = c.z; q[4*k+3] = c.w;
    }
    float mx = -3.4e38f;
#pragma unroll
    for (int k = 0; k < 16; k++) mx = fmaxf(mx, v[k]);
    mx = blkMax(mx, sh);
    float se = 0.f, qv = 0.f;
#pragma unroll
    for (int k = 0; k < 16; k++) { se += __expf(v[k] - mx); qv += q[k] * v[k]; }
    se = blkSum(se, sh);
    qv = blkSum(qv, sh);
    if (tid == 0) {
        float lse = mx + logf(se);
        atomicAdd(&g_acc, (double)(lse - qv) * (0.5 / (32.0 * 18.0)));
    }
}

// ---------------- K6: region loss (lse + bf16 prob dots, no exp) ----------------
__global__ void __launch_bounds__(256) k_region(const float* __restrict__ sreg) {
    __shared__ float sh[8];
    int row = blockIdx.x, tid = threadIdx.x;
    int j, b, s;
    if (row < 12544) { j = row / 6272; int r = row - j * 6272; b = r / NGLOB; s = r - b * NGLOB; }
    else { int lr = row - 12544; j = 2 + lr / 1152; int r = lr % 1152; b = r / NLOC; s = r - b * NLOC; }
    int S = (j < 2) ? NGLOB : NLOC;

    const float4* sp = (const float4*)(sreg + (size_t)row * DIM);
    float4 v[4];
#pragma unroll
    for (int k = 0; k < 4; k++) {
        float4 t = __ldcs(sp + tid + 256 * k);
        v[k] = make_float4(t.x * 10.f, t.y * 10.f, t.z * 10.f, t.w * 10.f);
    }
    float mx = -3.4e38f;
#pragma unroll
    for (int k = 0; k < 4; k++)
        mx = fmaxf(mx, fmaxf(fmaxf(v[k].x, v[k].y), fmaxf(v[k].z, v[k].w)));
    mx = blkMax(mx, sh);
    float se = 0.f;
#pragma unroll
    for (int k = 0; k < 4; k++)
        se += __expf(v[k].x - mx) + __expf(v[k].y - mx) + __expf(v[k].z - mx) + __expf(v[k].w - mx);
    se = blkSum(se, sh);
    float lse = mx + logf(se);

    int np, is0, is1;
    if (j == 0) { is0 = 1; is1 = 1; np = 1; }
    else if (j == 1) { is0 = 0; is1 = 0; np = 1; }
    else { is0 = 0; is1 = 1; np = 2; }

    float dotsum = 0.f;
    for (int qq = 0; qq < np; qq++) {
        int i = (qq == 0) ? is0 : is1;
        int p = (i == 0) ? ((j == 1) ? 0 : (j - 1)) : ((j == 0) ? 9 : (j + 8));
        unsigned long long key = g_best[c_POFF[p] + b * S + s];
        int n = 0xFFFF - (int)(key & 0xFFFFull);
        int trow = i * 6272 + b * NGLOB + n;
        const uint2* pp = g_tprob + (size_t)trow * (DIM / 4);
        float part = 0.f;
#pragma unroll
        for (int k = 0; k < 4; k++) {
            uint2 u = pp[tid + 256 * k];
            __nv_bfloat162 h0 = *reinterpret_cast<__nv_bfloat162*>(&u.x);
            __nv_bfloat162 h1 = *reinterpret_cast<__nv_bfloat162*>(&u.y);
            float2 f0 = __bfloat1622float2(h0);
            float2 f1 = __bfloat1622float2(h1);
            part += f0.x * v[k].x + f0.y * v[k].y + f1.x * v[k].z + f1.y * v[k].w;
        }
        part = blkSum(part, sh);
        dotsum += part;
    }
    if (tid == 0) {
        double contrib = ((double)np * (double)lse - (double)dotsum)
                       * (0.5 / ((double)S * 32.0 * 18.0));
        atomicAdd(&g_acc, contrib);
    }
}

// ---------------- K7: finalize ----------------
__global__ void k_fin(float* out) { out[0] = (float)g_acc; }

// ---------------- launch ----------------
extern "C" void kernel_launch(void* const* d_in, const int* in_sizes, int n_in,
                              void* d_out, int out_size) {
    (void)in_sizes; (void)n_in; (void)out_size;
    const float* s_cls  = (const float*)d_in[0];
    const float* s_reg  = (const float*)d_in[1];
    const float* s_fea  = (const float*)d_in[2];
    const float* t_cls  = (const float*)d_in[3];
    const float* t_reg  = (const float*)d_in[4];
    const float* t_fea  = (const float*)d_in[5];
    const float* center = (const float*)d_in[6];
    const float* cgrid  = (const float*)d_in[7];
    const int*   ep     = (const int*)d_in[8];

    k_init<<<121, 256>>>();
    k_norm<<<SROWS + TROWS, 128>>>(s_fea, t_fea);
    k_tcls<<<64, 256>>>(t_cls, center, ep);
    k_prob<<<TROWS, 256>>>(t_reg, cgrid, ep);
    k_sim<<<512, 256>>>();
    k_cls<<<dim3(18, NB), 256>>>(s_cls);
    k_region<<<SROWS, 256>>>(s_reg);
    k_fin<<<1, 1>>>((float*)d_out);
}